// round 5
// baseline (speedup 1.0000x reference)
#include <cuda_runtime.h>
#include <cstdint>

// GraphAttention: V=500000, D=128, B=4096, T=3, K=64  (rows = 12288)
// One warp per row. Warp compaction of active neighbors -> padded to a
// multiple of 16 with dummy id 0 (zero-weighted) -> software-pipelined
// double-buffered inner loop: while chunk i is reduced/accumulated, the
// 8 LDG.128 of chunk i+1 are already in flight (continuous MLP).
// Plain-C++ rewrite of the R3 design (two infra failures on the macro version).

#define NUM_ROWS  (4096 * 3)
#define KNEIGH    64
#define DDIM      128
#define INV_ATT_SCALE (1.0f / 15.0f)
#define LN_EPS    1e-5f
#define WPB       4
#define THREADS   (WPB * 32)
#define CHUNK     8

__device__ __forceinline__ float warp_sum(float v) {
    v += __shfl_xor_sync(0xffffffffu, v, 16);
    v += __shfl_xor_sync(0xffffffffu, v, 8);
    v += __shfl_xor_sync(0xffffffffu, v, 4);
    v += __shfl_xor_sync(0xffffffffu, v, 2);
    v += __shfl_xor_sync(0xffffffffu, v, 1);
    return v;
}

// Issue CHUNK gathers (512B each) into a register buffer.
__device__ __forceinline__ void load_chunk(float4 (&buf)[CHUNK],
                                           const int* __restrict__ list,
                                           int base,
                                           const float4* __restrict__ embv,
                                           int lane)
{
    #pragma unroll
    for (int j = 0; j < CHUNK; ++j) {
        const int nb = list[base + j];
        buf[j] = embv[(size_t)nb * 32 + lane];
    }
}

// Dot + butterfly reduce + weight-masked accumulate for CHUNK neighbors.
__device__ __forceinline__ void proc_chunk(const float4 (&buf)[CHUNK],
                                           int base, int cnt,
                                           const float4& node,
                                           float4& acc)
{
    float p[CHUNK];
    #pragma unroll
    for (int j = 0; j < CHUNK; ++j)
        p[j] = buf[j].x * node.x + buf[j].y * node.y
             + buf[j].z * node.z + buf[j].w * node.w;

    #pragma unroll
    for (int j = 0; j < CHUNK; ++j)
        p[j] = warp_sum(p[j]);   // independent butterfly chains interleave

    #pragma unroll
    for (int j = 0; j < CHUNK; ++j) {
        const float att = (base + j < cnt) ? p[j] * INV_ATT_SCALE : 0.0f;
        acc.x += att * buf[j].x;
        acc.y += att * buf[j].y;
        acc.z += att * buf[j].z;
        acc.w += att * buf[j].w;
    }
}

__global__ __launch_bounds__(THREADS)
void graph_attention_kernel(const int*   __restrict__ node_ids,      // [B,3]
                            const int*   __restrict__ neighbor_ids,  // [B,3,K]
                            const int*   __restrict__ neighbor_mask, // [B,3,K]
                            const float* __restrict__ emb,           // [V,D]
                            const float* __restrict__ gamma,         // [D]
                            const float* __restrict__ beta,          // [D]
                            float*       __restrict__ out)           // [B,3,D]
{
    __shared__ int s_act[WPB][KNEIGH];

    const int w    = threadIdx.x >> 5;
    const int lane = threadIdx.x & 31;
    const int row  = blockIdx.x * WPB + w;   // grid sized exactly

    const float4* __restrict__ embv = reinterpret_cast<const float4*>(emb);

    const int nid = node_ids[row];
    const float4 node = embv[(size_t)nid * 32 + lane];

    // ---- warp-level compaction of active neighbors ----
    const int* __restrict__ nids  = neighbor_ids  + (size_t)row * KNEIGH;
    const int* __restrict__ nmask = neighbor_mask + (size_t)row * KNEIGH;

    const int m0  = nmask[lane];
    const int m1  = nmask[lane + 32];
    const int id0 = nids[lane];
    const int id1 = nids[lane + 32];

    const unsigned full = 0xffffffffu;
    const unsigned b0 = __ballot_sync(full, m0 != 0);
    const unsigned b1 = __ballot_sync(full, m1 != 0);
    const int c0  = __popc(b0);
    const int cnt = c0 + __popc(b1);
    const unsigned lt = (1u << lane) - 1u;

    if (m0) s_act[w][__popc(b0 & lt)]      = id0;
    if (m1) s_act[w][c0 + __popc(b1 & lt)] = id1;

    // pad active list to a multiple of 16 with dummy id 0 (zero-weighted below)
    const int pad16 = (cnt + 15) & ~15;      // <= 64
    if (lane < pad16 - cnt) s_act[w][cnt + lane] = 0;
    __syncwarp(full);

    // ---- pipelined inner loop: 2 chunks of CHUNK per iteration ----
    float4 acc = make_float4(0.f, 0.f, 0.f, 0.f);
    float4 bufA[CHUNK], bufB[CHUNK];
    const int* __restrict__ list = s_act[w];

    const int np = pad16 >> 3;               // even: 0,2,4,6,8
    if (np > 0) {
        load_chunk(bufA, list, 0, embv, lane);
        for (int c = 0; c < np; c += 2) {
            load_chunk(bufB, list, (c + 1) * CHUNK, embv, lane); // in flight during proc(A)
            proc_chunk(bufA, c * CHUNK, cnt, node, acc);
            if (c + 2 < np)
                load_chunk(bufA, list, (c + 2) * CHUNK, embv, lane); // in flight during proc(B)
            proc_chunk(bufB, (c + 1) * CHUNK, cnt, node, acc);
        }
    }

    // ---- x = node + att_out, LayerNorm over D=128 ----
    float4 x;
    x.x = node.x + acc.x;
    x.y = node.y + acc.y;
    x.z = node.z + acc.z;
    x.w = node.w + acc.w;

    const float mu = warp_sum(x.x + x.y + x.z + x.w) * (1.0f / DDIM);

    const float dx0 = x.x - mu, dx1 = x.y - mu, dx2 = x.z - mu, dx3 = x.w - mu;
    const float var = warp_sum(dx0*dx0 + dx1*dx1 + dx2*dx2 + dx3*dx3) * (1.0f / DDIM);
    const float r = rsqrtf(var + LN_EPS);

    const float4 g = reinterpret_cast<const float4*>(gamma)[lane];
    const float4 b = reinterpret_cast<const float4*>(beta)[lane];

    float4 o;
    o.x = dx0 * r * g.x + b.x;
    o.y = dx1 * r * g.y + b.y;
    o.z = dx2 * r * g.z + b.z;
    o.w = dx3 * r * g.w + b.w;

    reinterpret_cast<float4*>(out)[(size_t)row * 32 + lane] = o;
}

extern "C" void kernel_launch(void* const* d_in, const int* in_sizes, int n_in,
                              void* d_out, int out_size)
{
    const int*   node_ids      = (const int*)  d_in[0];
    const int*   neighbor_ids  = (const int*)  d_in[1];
    const int*   neighbor_mask = (const int*)  d_in[2];
    const float* emb           = (const float*)d_in[3];
    const float* gamma         = (const float*)d_in[4];
    const float* beta          = (const float*)d_in[5];
    float*       out           = (float*)d_out;

    const int blocks = NUM_ROWS / WPB;       // 3072, exact

    graph_attention_kernel<<<blocks, THREADS>>>(node_ids, neighbor_ids, neighbor_mask,
                                                emb, gamma, beta, out);
}